// round 5
// baseline (speedup 1.0000x reference)
#include <cuda_runtime.h>
#include <math_constants.h>
#include <stdint.h>

#define KCODES 512
#define DDIM   64
#define NROW   65536
#define QELEMS 4194304
#define NBLK   128
#define NTHR   512           // 1 row per thread; 128*512 = 65536 exactly

__device__ double   g_partial[NBLK];
__device__ unsigned g_count = 0;

// smem: codebook 131072 B + norms 2048 B + reduce 4096 B = 137216 B
#define SMEM_BYTES (KCODES * DDIM * 4 + KCODES * 4 + NTHR * 8)

// ---------------------------------------------------------------------------
// Zero this block's 512 encoding rows (1 MB); enc base is d_out+4+4*QELEMS,
// i.e. only 4B aligned -> scalar fringes around a float4 interior.
// ---------------------------------------------------------------------------
__device__ __forceinline__ void zero_rows(float* __restrict__ enc,
                                          int row0, int nrows, int tid) {
    float* p = enc + (size_t)row0 * KCODES;
    int n = nrows * KCODES;
    uintptr_t a = (uintptr_t)p;
    int head = (int)((((a + 15) & ~(uintptr_t)15) - a) >> 2);   // 0..3 floats
    if (tid < head) p[tid] = 0.0f;
    int n4 = (n - head) >> 2;
    int tail = (n - head) & 3;
    float4* v = (float4*)(p + head);
    float4 z = make_float4(0.f, 0.f, 0.f, 0.f);
    for (int i = tid; i < n4; i += NTHR) v[i] = z;
    if (tid >= 4 && tid - 4 < tail) p[head + 4 * n4 + (tid - 4)] = 0.0f;
}

// ---------------------------------------------------------------------------
// Single fused kernel: codebook stage + enc zero-fill + norms + argmin +
// q_out + one-hot + loss (fence/atomic last-block final reduce).
// ---------------------------------------------------------------------------
__global__ void __launch_bounds__(NTHR) vq_fused(
    const float* __restrict__ x,
    const float* __restrict__ w,
    float* __restrict__ out,       // out[0]=loss
    float* __restrict__ qout,
    float* __restrict__ enc)
{
    extern __shared__ float sm[];
    float*  sw   = sm;                       // [512*64]
    float*  sb   = sm + KCODES * DDIM;       // [512]
    double* sred = (double*)(sb + KCODES);   // [512]

    const int tid = threadIdx.x;
    const int bid = blockIdx.x;

    // Stage codebook (coalesced float4; w is harness-aligned)
    {
        const float4* w4 = (const float4*)w;
        float4*       s4 = (float4*)sw;
        for (int i = tid; i < KCODES * DDIM / 4; i += NTHR) s4[i] = w4[i];
    }

    // Zero-fill exactly the 512 enc rows this block later writes ones into;
    // stores drain to DRAM underneath the FFMA loop.
    zero_rows(enc, bid * NTHR, NTHR, tid);

    __syncthreads();

    // Codebook norms — identical rounding chain to reference (one k per thread)
    {
        int k = tid;   // NTHR == KCODES
        float acc = 0.0f;
        #pragma unroll
        for (int d = 0; d < DDIM; d++) {
            float v = sw[k * DDIM + d];
            acc = __fadd_rn(acc, __fmul_rn(v, v));
        }
        sb[k] = acc;
    }
    __syncthreads();

    // One row per thread. x layout [B=64, D=64, H=32, W=32]:
    // row n -> gather stride 1024; consecutive tid -> coalesced.
    const int n = bid * NTHR + tid;
    const int b = n >> 10, hw = n & 1023;
    const float* p = x + (size_t)b * 65536 + hw;

    float xr[DDIM];
    #pragma unroll
    for (int d = 0; d < DDIM; d++) xr[d] = p[d * 1024];

    // a = sum(x*x): fp32 sequential, products rounded separately (no FMA)
    float a = 0.0f;
    #pragma unroll
    for (int d = 0; d < DDIM; d++)
        a = __fadd_rn(a, __fmul_rn(xr[d], xr[d]));

    float best = CUDART_INF_F;
    int   bi   = 0;

    // Main loop: 2 codes per iteration = 2 independent FMA chains per thread;
    // 4 warps/SMSP cover LDS latency. All codebook LDS are warp-broadcast.
    for (int k0 = 0; k0 < KCODES; k0 += 2) {
        const float4* w0 = (const float4*)(sw + (k0 << 6));
        float ma = 0.0f, mb = 0.0f;
        #pragma unroll
        for (int j = 0; j < 16; j++) {
            float4 u = w0[j];        // code k0
            float4 v = w0[j + 16];   // code k0+1
            ma = __fmaf_rn(xr[4*j+0], u.x, ma);
            ma = __fmaf_rn(xr[4*j+1], u.y, ma);
            ma = __fmaf_rn(xr[4*j+2], u.z, ma);
            ma = __fmaf_rn(xr[4*j+3], u.w, ma);
            mb = __fmaf_rn(xr[4*j+0], v.x, mb);
            mb = __fmaf_rn(xr[4*j+1], v.y, mb);
            mb = __fmaf_rn(xr[4*j+2], v.z, mb);
            mb = __fmaf_rn(xr[4*j+3], v.w, mb);
        }
        // d = fl( fl(a + b) - fl(2*m) ) — exact reference rounding structure
        float d0 = __fsub_rn(__fadd_rn(a, sb[k0]),     __fmul_rn(2.0f, ma));
        float d1 = __fsub_rn(__fadd_rn(a, sb[k0 + 1]), __fmul_rn(2.0f, mb));
        if (d0 < best) { best = d0; bi = k0; }       // strict <: first index
        if (d1 < best) { best = d1; bi = k0 + 1; }
    }

    // Epilogue: straight-through q_out (bit-replicated), one-hot one, loss
    double ls = 0.0;
    {
        float* qp = qout + (size_t)b * 65536 + hw;
        const float* wq = sw + bi * DDIM;
        #pragma unroll
        for (int d = 0; d < DDIM; d++) {
            float diff = __fsub_rn(wq[d], xr[d]);
            qp[d * 1024] = __fadd_rn(xr[d], diff);
            ls += (double)__fmul_rn(diff, diff);
        }
        enc[(size_t)n * KCODES + bi] = 1.0f;
    }

    // Deterministic block-level loss reduction (fixed tree)
    sred[tid] = ls;
    __syncthreads();
    for (int s = NTHR / 2; s > 0; s >>= 1) {
        if (tid < s) sred[tid] += sred[tid + s];
        __syncthreads();
    }

    // Last-block final reduce (canonical fence + atomic idiom; deterministic
    // because the final sum is over g_partial[] in fixed index order).
    __shared__ int isLast;
    if (tid == 0) {
        g_partial[bid] = sred[0];
        __threadfence();
        unsigned old = atomicAdd(&g_count, 1u);
        isLast = (old == NBLK - 1u) ? 1 : 0;
    }
    __syncthreads();
    if (isLast) {
        double v = (tid < NBLK) ? g_partial[tid] : 0.0;
        sred[tid] = v;
        __syncthreads();
        for (int s = NTHR / 2; s > 0; s >>= 1) {
            if (tid < s) sred[tid] += sred[tid + s];
            __syncthreads();
        }
        if (tid == 0) {
            float m = (float)(sred[0] / (double)QELEMS);
            out[0] = __fadd_rn(m, __fmul_rn(0.25f, m));  // z_q + 0.25*z_e
            g_count = 0;                                 // reset for replay
        }
    }
}

// ---------------------------------------------------------------------------
extern "C" void kernel_launch(void* const* d_in, const int* in_sizes, int n_in,
                              void* d_out, int out_size) {
    const float* x = (const float*)d_in[0];   // [64,64,32,32] fp32
    const float* w = (const float*)d_in[1];   // [512,64] fp32
    float* out  = (float*)d_out;
    float* qout = out + 1;                    // [4194304] (4B-aligned only)
    float* enc  = out + 1 + QELEMS;           // [65536*512] (4B-aligned only)

    cudaFuncSetAttribute(vq_fused, cudaFuncAttributeMaxDynamicSharedMemorySize,
                         SMEM_BYTES);

    vq_fused<<<NBLK, NTHR, SMEM_BYTES>>>(x, w, out, qout, enc);
}

// round 6
// speedup vs baseline: 1.0837x; 1.0837x over previous
#include <cuda_runtime.h>
#include <math_constants.h>
#include <stdint.h>

#define KCODES 512
#define DDIM   64
#define NROW   65536
#define QELEMS 4194304
#define NBLK   148
#define NTHR   448            // 14 warps; reg budget 64K/448 = 146 (no 128 cap)
#define NWARP  14
#define NUNITS 2048           // 65536 rows / 32 rows-per-warp-unit

__device__ double   g_partial[NBLK];
__device__ unsigned g_count = 0;

// smem: codebook 131072 + norms 2048 + reduce 3584 = 136704 B
#define SMEM_BYTES (KCODES * DDIM * 4 + KCODES * 4 + NTHR * 8)

// ---------------------------------------------------------------------------
// Zero 32 encoding rows (one unit, 64 KB) with one warp; enc base is only
// 4B-aligned (d_out+4+4*QELEMS) -> scalar fringes around float4 interior.
// ---------------------------------------------------------------------------
__device__ __forceinline__ void zero_unit(float* __restrict__ enc,
                                          int unit, int lane) {
    float* p = enc + (size_t)unit * 32 * KCODES;
    const int n = 32 * KCODES;                 // 16384 floats
    uintptr_t a = (uintptr_t)p;
    int head = (int)((((a + 15) & ~(uintptr_t)15) - a) >> 2);  // 0..3
    if (lane < head) p[lane] = 0.0f;
    int n4 = (n - head) >> 2;
    int tail = (n - head) & 3;
    float4* v = (float4*)(p + head);
    float4 z = make_float4(0.f, 0.f, 0.f, 0.f);
    for (int i = lane; i < n4; i += 32) v[i] = z;
    if (lane >= 4 && lane - 4 < tail) p[head + 4 * n4 + (lane - 4)] = 0.0f;
}

// ---------------------------------------------------------------------------
// Fused kernel. Work unit = 1 warp x 32 rows x all 512 codes.
// Unit u -> block (u % 148), warp (u / 148): busiest SM gets 14 units.
// ---------------------------------------------------------------------------
__global__ void __launch_bounds__(NTHR, 1) vq_fused(
    const float* __restrict__ x,
    const float* __restrict__ w,
    float* __restrict__ out,       // out[0] = loss
    float* __restrict__ qout,
    float* __restrict__ enc)
{
    extern __shared__ float sm[];
    float*  sw   = sm;                       // [512*64]
    float*  sb   = sm + KCODES * DDIM;       // [512]
    double* sred = (double*)(sb + KCODES);   // [448]

    const int tid  = threadIdx.x;
    const int bid  = blockIdx.x;
    const int wid  = tid >> 5;
    const int lane = tid & 31;
    const int unit = bid + NBLK * wid;       // striped unit id
    const bool active = (unit < NUNITS);

    // Stage codebook (coalesced float4; w is harness-aligned)
    {
        const float4* w4 = (const float4*)w;
        float4*       s4 = (float4*)sw;
        for (int i = tid; i < KCODES * DDIM / 4; i += NTHR) s4[i] = w4[i];
    }

    // Zero-fill this warp's unit rows in enc (drains under the FFMA loop)
    if (active) zero_unit(enc, unit, lane);

    __syncthreads();

    // Codebook norms — identical rounding chain to reference
    for (int k = tid; k < KCODES; k += NTHR) {
        float acc = 0.0f;
        #pragma unroll
        for (int d = 0; d < DDIM; d++) {
            float v = sw[k * DDIM + d];
            acc = __fadd_rn(acc, __fmul_rn(v, v));
        }
        sb[k] = acc;
    }
    __syncthreads();

    double ls = 0.0;

    if (active) {
        // One row per lane. x layout [B=64, D=64, H=32, W=32]:
        // row n -> base (n>>10)*65536 + (n&1023), gather stride 1024.
        const int n = unit * 32 + lane;
        const int b = n >> 10, hw = n & 1023;
        const float* p = x + (size_t)b * 65536 + hw;

        float xr[DDIM];
        #pragma unroll
        for (int d = 0; d < DDIM; d++) xr[d] = p[d * 1024];

        // a = sum(x*x): fp32 sequential, rounded mul then add (no FMA)
        float a = 0.0f;
        #pragma unroll
        for (int d = 0; d < DDIM; d++)
            a = __fadd_rn(a, __fmul_rn(xr[d], xr[d]));

        float best = CUDART_INF_F;
        int   bi   = 0;

        // Main loop: 2 codes/iter = 2 independent FMA chains; broadcast LDS.
        #pragma unroll 1
        for (int k0 = 0; k0 < KCODES; k0 += 2) {
            const float4* w0 = (const float4*)(sw + (k0 << 6));
            float ma = 0.0f, mb = 0.0f;
            #pragma unroll
            for (int j = 0; j < 16; j++) {
                float4 u = w0[j];        // code k0
                float4 v = w0[j + 16];   // code k0+1
                ma = __fmaf_rn(xr[4*j+0], u.x, ma);
                ma = __fmaf_rn(xr[4*j+1], u.y, ma);
                ma = __fmaf_rn(xr[4*j+2], u.z, ma);
                ma = __fmaf_rn(xr[4*j+3], u.w, ma);
                mb = __fmaf_rn(xr[4*j+0], v.x, mb);
                mb = __fmaf_rn(xr[4*j+1], v.y, mb);
                mb = __fmaf_rn(xr[4*j+2], v.z, mb);
                mb = __fmaf_rn(xr[4*j+3], v.w, mb);
            }
            // d = fl( fl(a + b) - fl(2*m) ) — exact reference rounding
            float d0 = __fsub_rn(__fadd_rn(a, sb[k0]),     __fmul_rn(2.0f, ma));
            float d1 = __fsub_rn(__fadd_rn(a, sb[k0 + 1]), __fmul_rn(2.0f, mb));
            if (d0 < best) { best = d0; bi = k0; }      // strict <: first index
            if (d1 < best) { best = d1; bi = k0 + 1; }
        }

        // Epilogue: straight-through q_out (bit-replicated), one-hot, loss
        float* qp = qout + (size_t)b * 65536 + hw;
        const float* wq = sw + bi * DDIM;
        #pragma unroll
        for (int d = 0; d < DDIM; d++) {
            float diff = __fsub_rn(wq[d], xr[d]);
            qp[d * 1024] = __fadd_rn(xr[d], diff);
            ls += (double)__fmul_rn(diff, diff);
        }
        enc[(size_t)n * KCODES + bi] = 1.0f;
    }

    // Deterministic block-level loss reduction (fixed tree over 448 slots)
    sred[tid] = ls;
    __syncthreads();
    if (tid < 192) sred[tid] += sred[tid + 256];   // 448 -> 256
    __syncthreads();
    for (int s = 128; s > 0; s >>= 1) {
        if (tid < s) sred[tid] += sred[tid + s];
        __syncthreads();
    }

    // Last-block final reduce (fence+atomic; deterministic fixed-order sum)
    __shared__ int isLast;
    if (tid == 0) {
        g_partial[bid] = sred[0];
        __threadfence();
        unsigned old = atomicAdd(&g_count, 1u);
        isLast = (old == NBLK - 1u) ? 1 : 0;
    }
    __syncthreads();
    if (isLast) {
        double v = (tid < NBLK) ? g_partial[tid] : 0.0;
        sred[tid] = v;                               // 448 slots, 148 used
        __syncthreads();
        if (tid < 192) sred[tid] += sred[tid + 256];
        __syncthreads();
        for (int s = 128; s > 0; s >>= 1) {
            if (tid < s) sred[tid] += sred[tid + s];
            __syncthreads();
        }
        if (tid == 0) {
            float m = (float)(sred[0] / (double)QELEMS);
            out[0] = __fadd_rn(m, __fmul_rn(0.25f, m));  // z_q + 0.25*z_e
            g_count = 0;                                 // reset for replay
        }
    }
}

// ---------------------------------------------------------------------------
extern "C" void kernel_launch(void* const* d_in, const int* in_sizes, int n_in,
                              void* d_out, int out_size) {
    const float* x = (const float*)d_in[0];   // [64,64,32,32] fp32
    const float* w = (const float*)d_in[1];   // [512,64] fp32
    float* out  = (float*)d_out;
    float* qout = out + 1;                    // [4194304] (4B-aligned only)
    float* enc  = out + 1 + QELEMS;           // [65536*512] (4B-aligned only)

    cudaFuncSetAttribute(vq_fused, cudaFuncAttributeMaxDynamicSharedMemorySize,
                         SMEM_BYTES);

    vq_fused<<<NBLK, NTHR, SMEM_BYTES>>>(x, w, out, qout, enc);
}

// round 7
// speedup vs baseline: 1.2576x; 1.1605x over previous
#include <cuda_runtime.h>
#include <math_constants.h>
#include <stdint.h>

#define KCODES 512
#define DDIM   64
#define NROW   65536
#define QELEMS 4194304
#define NBLK   148
#define NTHR   256            // 8 warps; reg budget 64K/256 = 255 -> no spill
#define MAXROWS 448           // max rows per block (7 rowsets x 64)

__device__ double   g_partial[NBLK];
__device__ unsigned g_count = 0;

// smem floats: sw 32768 | sb 512 | mbb 4*448 | mbi 4*448 | sred 256 doubles
#define SMEM_BYTES (32768*4 + 512*4 + 4*448*4 + 4*448*4 + 256*8)   // 149504

// ---------------------------------------------------------------------------
// Zero this block's encoding rows; enc base is only 4B-aligned
// (d_out+4+4*QELEMS) -> scalar fringes around a float4 interior.
// ---------------------------------------------------------------------------
__device__ __forceinline__ void zero_rows(float* __restrict__ enc,
                                          int row0, int nrows, int tid) {
    float* p = enc + (size_t)row0 * KCODES;
    int n = nrows * KCODES;
    uintptr_t a = (uintptr_t)p;
    int head = (int)((((a + 15) & ~(uintptr_t)15) - a) >> 2);   // 0..3
    if (tid < head) p[tid] = 0.0f;
    int n4 = (n - head) >> 2;
    int tail = (n - head) & 3;
    float4* v = (float4*)(p + head);
    float4 z = make_float4(0.f, 0.f, 0.f, 0.f);
    for (int i = tid; i < n4; i += NTHR) v[i] = z;
    if (tid >= 4 && tid - 4 < tail) p[head + 4 * n4 + (tid - 4)] = 0.0f;
}

// ---------------------------------------------------------------------------
// Fused kernel. Job = 1 warp x 64 rows (2/lane) x 128 codes (one k-quarter).
// 28 jobs/block on 8 warps -> every SMSP pair gets exactly 7 jobs.
// All codebook LDS are warp-broadcast (whole warp on one code) -> no conflicts.
// ---------------------------------------------------------------------------
__global__ void __launch_bounds__(NTHR, 1) vq_fused(
    const float* __restrict__ x,
    const float* __restrict__ w,
    float* __restrict__ out,       // out[0] = loss
    float* __restrict__ qout,
    float* __restrict__ enc)
{
    extern __shared__ float sm[];
    float*  sw   = sm;                         // [512*64]
    float*  sb   = sm + 32768;                 // [512]
    float*  mbb  = sb + 512;                   // [4][448] partial best dist
    int*    mbi  = (int*)(mbb + 4 * 448);      // [4][448] partial best idx
    double* sred = (double*)(mbi + 4 * 448);   // [256]

    const int tid  = threadIdx.x;
    const int bid  = blockIdx.x;
    const int wid  = tid >> 5;
    const int lane = tid & 31;

    // Block -> contiguous run of 64-row rowsets: 136 blocks x 7, 12 blocks x 6
    const int cnt   = (bid < 136) ? 7 : 6;
    const int rs0   = (bid < 136) ? bid * 7 : 952 + (bid - 136) * 6;
    const int row0  = rs0 * 64;
    const int nrows = cnt * 64;
    const int njobs = cnt * 4;

    // Stage codebook (coalesced float4; w is harness-aligned)
    {
        const float4* w4 = (const float4*)w;
        float4*       s4 = (float4*)sw;
        for (int i = tid; i < 8192; i += NTHR) s4[i] = w4[i];
    }

    // Zero-fill exactly this block's enc rows (drains under the FFMA loop)
    zero_rows(enc, row0, nrows, tid);

    __syncthreads();

    // Codebook norms — identical rounding chain to reference
    for (int k = tid; k < KCODES; k += NTHR) {
        float acc = 0.0f;
        #pragma unroll
        for (int d = 0; d < DDIM; d++) {
            float v = sw[k * DDIM + d];
            acc = __fadd_rn(acc, __fmul_rn(v, v));
        }
        sb[k] = acc;
    }
    __syncthreads();

    // ---------------- Main phase: quarter-jobs ----------------------------
    // Warp w handles jobs jj = w, w+8, w+16, w+24 (< njobs).
    #pragma unroll 1
    for (int i = 0; i < 4; i++) {
        int jj = wid + 8 * i;
        if (jj >= njobs) break;
        const int rsl = jj >> 2;            // local rowset 0..cnt-1
        const int q   = jj & 3;             // code quarter 0..3
        const int n0 = row0 + rsl * 64 + lane;
        const int n1 = n0 + 32;

        // x layout [B=64, D=64, H=32, W=32]: row n -> gather stride 1024
        float xr0[DDIM], xr1[DDIM];
        {
            int b = n0 >> 10, hw = n0 & 1023;
            const float* p = x + (size_t)b * 65536 + hw;
            #pragma unroll
            for (int d = 0; d < DDIM; d++) xr0[d] = p[d * 1024];
        }
        {
            int b = n1 >> 10, hw = n1 & 1023;
            const float* p = x + (size_t)b * 65536 + hw;
            #pragma unroll
            for (int d = 0; d < DDIM; d++) xr1[d] = p[d * 1024];
        }

        // a = sum(x*x): fp32 sequential, rounded mul then add (no FMA)
        float a0 = 0.0f, a1 = 0.0f;
        #pragma unroll
        for (int d = 0; d < DDIM; d++) {
            a0 = __fadd_rn(a0, __fmul_rn(xr0[d], xr0[d]));
            a1 = __fadd_rn(a1, __fmul_rn(xr1[d], xr1[d]));
        }

        float best0 = CUDART_INF_F, best1 = CUDART_INF_F;
        int   bi0 = 0, bi1 = 0;
        const int kbase = q << 7;           // 128 codes per quarter

        #pragma unroll 1
        for (int kk = 0; kk < 128; kk += 2) {
            const int k0 = kbase + kk;
            const float4* w0 = (const float4*)(sw + (k0 << 6));
            float ma0 = 0.0f, mb0 = 0.0f, ma1 = 0.0f, mb1 = 0.0f;
            #pragma unroll
            for (int j = 0; j < 16; j++) {
                float4 u = w0[j];        // code k0
                float4 v = w0[j + 16];   // code k0+1
                ma0 = __fmaf_rn(xr0[4*j+0], u.x, ma0);
                ma0 = __fmaf_rn(xr0[4*j+1], u.y, ma0);
                ma0 = __fmaf_rn(xr0[4*j+2], u.z, ma0);
                ma0 = __fmaf_rn(xr0[4*j+3], u.w, ma0);
                mb0 = __fmaf_rn(xr0[4*j+0], v.x, mb0);
                mb0 = __fmaf_rn(xr0[4*j+1], v.y, mb0);
                mb0 = __fmaf_rn(xr0[4*j+2], v.z, mb0);
                mb0 = __fmaf_rn(xr0[4*j+3], v.w, mb0);
                ma1 = __fmaf_rn(xr1[4*j+0], u.x, ma1);
                ma1 = __fmaf_rn(xr1[4*j+1], u.y, ma1);
                ma1 = __fmaf_rn(xr1[4*j+2], u.z, ma1);
                ma1 = __fmaf_rn(xr1[4*j+3], u.w, ma1);
                mb1 = __fmaf_rn(xr1[4*j+0], v.x, mb1);
                mb1 = __fmaf_rn(xr1[4*j+1], v.y, mb1);
                mb1 = __fmaf_rn(xr1[4*j+2], v.z, mb1);
                mb1 = __fmaf_rn(xr1[4*j+3], v.w, mb1);
            }
            float b0 = sb[k0], b1 = sb[k0 + 1];
            // d = fl( fl(a + b) - fl(2*m) ) — exact reference rounding
            float d00 = __fsub_rn(__fadd_rn(a0, b0), __fmul_rn(2.0f, ma0));
            float d01 = __fsub_rn(__fadd_rn(a0, b1), __fmul_rn(2.0f, mb0));
            float d10 = __fsub_rn(__fadd_rn(a1, b0), __fmul_rn(2.0f, ma1));
            float d11 = __fsub_rn(__fadd_rn(a1, b1), __fmul_rn(2.0f, mb1));
            if (d00 < best0) { best0 = d00; bi0 = k0; }
            if (d01 < best0) { best0 = d01; bi0 = k0 + 1; }
            if (d10 < best1) { best1 = d10; bi1 = k0; }
            if (d11 < best1) { best1 = d11; bi1 = k0 + 1; }
        }

        // Store partials; [q][row] layout -> consecutive lanes, no conflicts
        int r0 = rsl * 64 + lane;
        mbb[q * MAXROWS + r0]      = best0;
        mbb[q * MAXROWS + r0 + 32] = best1;
        mbi[q * MAXROWS + r0]      = bi0;
        mbi[q * MAXROWS + r0 + 32] = bi1;
    }
    __syncthreads();

    // ---------------- Epilogue: merge quarters + outputs -------------------
    double ls = 0.0;
    for (int rl = tid; rl < nrows; rl += NTHR) {
        // Ascending-q merge with strict < == global first-index argmin
        float best = CUDART_INF_F; int bi = 0;
        #pragma unroll
        for (int q = 0; q < 4; q++) {
            float d = mbb[q * MAXROWS + rl];
            int   k = mbi[q * MAXROWS + rl];
            if (d < best) { best = d; bi = k; }
        }
        const int n = row0 + rl;
        const int b = n >> 10, hw = n & 1023;
        const float* p  = x    + (size_t)b * 65536 + hw;
        float*       qp = qout + (size_t)b * 65536 + hw;
        const float* wq = sw + bi * DDIM;
        #pragma unroll
        for (int d = 0; d < DDIM; d++) {
            float xv   = p[d * 1024];
            float diff = __fsub_rn(wq[d], xv);
            qp[d * 1024] = __fadd_rn(xv, diff);     // straight-through
            ls += (double)__fmul_rn(diff, diff);
        }
        enc[(size_t)n * KCODES + bi] = 1.0f;
    }

    // Deterministic block-level loss reduction (fixed tree)
    sred[tid] = ls;
    __syncthreads();
    for (int s = NTHR / 2; s > 0; s >>= 1) {
        if (tid < s) sred[tid] += sred[tid + s];
        __syncthreads();
    }

    // Last-block final reduce (fence+atomic; deterministic fixed-order sum)
    __shared__ int isLast;
    if (tid == 0) {
        g_partial[bid] = sred[0];
        __threadfence();
        unsigned old = atomicAdd(&g_count, 1u);
        isLast = (old == NBLK - 1u) ? 1 : 0;
    }
    __syncthreads();
    if (isLast) {
        sred[tid] = (tid < NBLK) ? g_partial[tid] : 0.0;
        __syncthreads();
        for (int s = NTHR / 2; s > 0; s >>= 1) {
            if (tid < s) sred[tid] += sred[tid + s];
            __syncthreads();
        }
        if (tid == 0) {
            float m = (float)(sred[0] / (double)QELEMS);
            out[0] = __fadd_rn(m, __fmul_rn(0.25f, m));  // z_q + 0.25*z_e
            g_count = 0;                                 // reset for replay
        }
    }
}

// ---------------------------------------------------------------------------
extern "C" void kernel_launch(void* const* d_in, const int* in_sizes, int n_in,
                              void* d_out, int out_size) {
    const float* x = (const float*)d_in[0];   // [64,64,32,32] fp32
    const float* w = (const float*)d_in[1];   // [512,64] fp32
    float* out  = (float*)d_out;
    float* qout = out + 1;                    // [4194304] (4B-aligned only)
    float* enc  = out + 1 + QELEMS;           // [65536*512] (4B-aligned only)

    cudaFuncSetAttribute(vq_fused, cudaFuncAttributeMaxDynamicSharedMemorySize,
                         SMEM_BYTES);

    vq_fused<<<NBLK, NTHR, SMEM_BYTES>>>(x, w, out, qout, enc);
}